// round 1
// baseline (speedup 1.0000x reference)
#include <cuda_runtime.h>
#include <cuda_bf16.h>
#include <math.h>

// Problem constants
#define SEQ 8192
#define IN_DIM 1024
#define HID 2048
#define NEXP 8
#define TOPK 2
#define NTOK (SEQ * TOPK)   // 16384 dispatched rows

// Tiling
#define BM 128
#define BN 128
#define BK 16
#define NTHREADS 256

#define PERM_MAX (NTOK + NEXP * BM)   // 17408 padded rows max

// ---------------- device scratch (static, no allocation) ----------------
__device__ int g_count[NEXP];
__device__ int g_fill[NEXP];
__device__ int g_pbase[NEXP + 1];
__device__ int g_perm[PERM_MAX];

__device__ __align__(16) float g_hid[(size_t)PERM_MAX * HID];  // h, then act in-place
__device__ __align__(16) float g_gat[(size_t)PERM_MAX * HID];  // gate pre-activation
__device__ __align__(16) float g_y[(size_t)NTOK * IN_DIM];     // per-slot expert output

// ---------------- routing kernels ----------------
__global__ void k_init() {
    int i = blockIdx.x * blockDim.x + threadIdx.x;
    if (i < NEXP) { g_count[i] = 0; g_fill[i] = 0; }
    for (int j = i; j < PERM_MAX; j += gridDim.x * blockDim.x) g_perm[j] = -1;
}

__global__ void k_count(const int* __restrict__ sel) {
    int s = blockIdx.x * blockDim.x + threadIdx.x;
    if (s < NTOK) atomicAdd(&g_count[sel[s]], 1);
}

__global__ void k_scan() {
    if (threadIdx.x == 0) {
        int acc = 0;
        g_pbase[0] = 0;
        for (int e = 0; e < NEXP; e++) {
            acc += ((g_count[e] + BM - 1) / BM) * BM;
            g_pbase[e + 1] = acc;
        }
    }
}

__global__ void k_scatter(const int* __restrict__ sel) {
    int s = blockIdx.x * blockDim.x + threadIdx.x;
    if (s < NTOK) {
        int e = sel[s];
        int pos = g_pbase[e] + atomicAdd(&g_fill[e], 1);
        g_perm[pos] = s;
    }
}

// ---------------- GEMM1: x (gathered) @ W^T for up & gate ----------------
// A: [rows, IN_DIM] gathered via perm; B: W rows are hidden units, K-contiguous (NT gemm)
__global__ __launch_bounds__(NTHREADS) void k_gemm1(
    const float* __restrict__ inp,
    const float* __restrict__ up,
    const float* __restrict__ gate)
{
    int mt = blockIdx.x, nt = blockIdx.y, which = blockIdx.z;
    int row0 = mt * BM;
    int total = g_pbase[NEXP];
    if (row0 >= total) return;

    int e = 0;
    while (row0 >= g_pbase[e + 1]) e++;

    const float* W = (which == 0 ? up : gate)
                     + (size_t)e * HID * IN_DIM + (size_t)nt * BN * IN_DIM;
    float* Out = (which == 0 ? g_hid : g_gat);

    __shared__ float As[BK][BM];
    __shared__ float Bs[BK][BN];
    __shared__ int rowtok[BM];

    int tid = threadIdx.x;
    if (tid < BM) {
        int slot = g_perm[row0 + tid];
        rowtok[tid] = (slot >= 0) ? (slot >> 1) : -1;
    }
    __syncthreads();

    int tm = (tid >> 4) << 3;
    int tn = (tid & 15) << 3;

    float acc[8][8];
    #pragma unroll
    for (int i = 0; i < 8; i++)
        #pragma unroll
        for (int j = 0; j < 8; j++) acc[i][j] = 0.f;

    for (int k0 = 0; k0 < IN_DIM; k0 += BK) {
        #pragma unroll
        for (int l = 0; l < 2; l++) {
            int idx = tid + l * NTHREADS;       // 0..511
            int r = idx >> 2;                   // row 0..127
            int c4 = idx & 3;                   // float4 within 16-wide k slab
            int tok = rowtok[r];
            float4 v = make_float4(0.f, 0.f, 0.f, 0.f);
            if (tok >= 0)
                v = *(const float4*)(inp + (size_t)tok * IN_DIM + k0 + c4 * 4);
            As[c4 * 4 + 0][r] = v.x; As[c4 * 4 + 1][r] = v.y;
            As[c4 * 4 + 2][r] = v.z; As[c4 * 4 + 3][r] = v.w;
        }
        #pragma unroll
        for (int l = 0; l < 2; l++) {
            int idx = tid + l * NTHREADS;
            int r = idx >> 2;
            int c4 = idx & 3;
            float4 v = *(const float4*)(W + (size_t)r * IN_DIM + k0 + c4 * 4);
            Bs[c4 * 4 + 0][r] = v.x; Bs[c4 * 4 + 1][r] = v.y;
            Bs[c4 * 4 + 2][r] = v.z; Bs[c4 * 4 + 3][r] = v.w;
        }
        __syncthreads();

        #pragma unroll
        for (int k = 0; k < BK; k++) {
            float4 a0 = *(const float4*)&As[k][tm];
            float4 a1 = *(const float4*)&As[k][tm + 4];
            float4 b0 = *(const float4*)&Bs[k][tn];
            float4 b1 = *(const float4*)&Bs[k][tn + 4];
            float a[8] = {a0.x, a0.y, a0.z, a0.w, a1.x, a1.y, a1.z, a1.w};
            float b[8] = {b0.x, b0.y, b0.z, b0.w, b1.x, b1.y, b1.z, b1.w};
            #pragma unroll
            for (int i = 0; i < 8; i++)
                #pragma unroll
                for (int j = 0; j < 8; j++)
                    acc[i][j] = fmaf(a[i], b[j], acc[i][j]);
        }
        __syncthreads();
    }

    #pragma unroll
    for (int i = 0; i < 8; i++) {
        size_t o = (size_t)(row0 + tm + i) * HID + nt * BN + tn;
        *(float4*)&Out[o]     = make_float4(acc[i][0], acc[i][1], acc[i][2], acc[i][3]);
        *(float4*)&Out[o + 4] = make_float4(acc[i][4], acc[i][5], acc[i][6], acc[i][7]);
    }
}

// ---------------- gelu(g)*h, act written in-place into g_hid ----------------
__device__ __forceinline__ float gelu_tanh(float x) {
    float x3 = x * x * x;
    return 0.5f * x * (1.f + tanhf(0.7978845608028654f * (x + 0.044715f * x3)));
}

__global__ void k_act() {
    size_t total = (size_t)g_pbase[NEXP] * HID;
    size_t stride = (size_t)gridDim.x * blockDim.x * 4;
    for (size_t idx = ((size_t)blockIdx.x * blockDim.x + threadIdx.x) * 4;
         idx < total; idx += stride) {
        float4 g = *(float4*)&g_gat[idx];
        float4 h = *(float4*)&g_hid[idx];
        float4 r;
        r.x = gelu_tanh(g.x) * h.x;
        r.y = gelu_tanh(g.y) * h.y;
        r.z = gelu_tanh(g.z) * h.z;
        r.w = gelu_tanh(g.w) * h.w;
        *(float4*)&g_hid[idx] = r;
    }
}

// ---------------- GEMM2: act @ W_down (NN gemm), scatter rows to g_y ----------------
__global__ __launch_bounds__(NTHREADS) void k_gemm2(const float* __restrict__ down)
{
    int mt = blockIdx.x, nt = blockIdx.y;
    int row0 = mt * BM;
    int total = g_pbase[NEXP];
    if (row0 >= total) return;

    int e = 0;
    while (row0 >= g_pbase[e + 1]) e++;

    const float* W = down + (size_t)e * HID * IN_DIM;   // [HID, IN_DIM], n-contiguous
    int d0 = nt * BN;

    __shared__ float As[BK][BM];
    __shared__ float Bs[BK][BN];
    __shared__ int rowslot[BM];

    int tid = threadIdx.x;
    if (tid < BM) rowslot[tid] = g_perm[row0 + tid];
    __syncthreads();

    int tm = (tid >> 4) << 3;
    int tn = (tid & 15) << 3;

    float acc[8][8];
    #pragma unroll
    for (int i = 0; i < 8; i++)
        #pragma unroll
        for (int j = 0; j < 8; j++) acc[i][j] = 0.f;

    for (int k0 = 0; k0 < HID; k0 += BK) {
        #pragma unroll
        for (int l = 0; l < 2; l++) {
            int idx = tid + l * NTHREADS;
            int r = idx >> 2;
            int c4 = idx & 3;
            float4 v = *(const float4*)(g_hid + (size_t)(row0 + r) * HID + k0 + c4 * 4);
            As[c4 * 4 + 0][r] = v.x; As[c4 * 4 + 1][r] = v.y;
            As[c4 * 4 + 2][r] = v.z; As[c4 * 4 + 3][r] = v.w;
        }
        #pragma unroll
        for (int l = 0; l < 2; l++) {
            int idx = tid + l * NTHREADS;   // 0..511
            int r = idx >> 5;               // k row 0..15
            int c4 = idx & 31;              // 32 float4 across 128 n
            float4 v = *(const float4*)(W + (size_t)(k0 + r) * IN_DIM + d0 + c4 * 4);
            *(float4*)&Bs[r][c4 * 4] = v;
        }
        __syncthreads();

        #pragma unroll
        for (int k = 0; k < BK; k++) {
            float4 a0 = *(const float4*)&As[k][tm];
            float4 a1 = *(const float4*)&As[k][tm + 4];
            float4 b0 = *(const float4*)&Bs[k][tn];
            float4 b1 = *(const float4*)&Bs[k][tn + 4];
            float a[8] = {a0.x, a0.y, a0.z, a0.w, a1.x, a1.y, a1.z, a1.w};
            float b[8] = {b0.x, b0.y, b0.z, b0.w, b1.x, b1.y, b1.z, b1.w};
            #pragma unroll
            for (int i = 0; i < 8; i++)
                #pragma unroll
                for (int j = 0; j < 8; j++)
                    acc[i][j] = fmaf(a[i], b[j], acc[i][j]);
        }
        __syncthreads();
    }

    #pragma unroll
    for (int i = 0; i < 8; i++) {
        int slot = rowslot[tm + i];
        if (slot >= 0) {
            size_t o = (size_t)slot * IN_DIM + d0 + tn;
            *(float4*)&g_y[o]     = make_float4(acc[i][0], acc[i][1], acc[i][2], acc[i][3]);
            *(float4*)&g_y[o + 4] = make_float4(acc[i][4], acc[i][5], acc[i][6], acc[i][7]);
        }
    }
}

// ---------------- combine: out[t] = w0*y[2t] + w1*y[2t+1] ----------------
__global__ void k_combine(const float* __restrict__ wts, float* __restrict__ out) {
    size_t idx4 = ((size_t)blockIdx.x * blockDim.x + threadIdx.x) * 4;
    if (idx4 >= (size_t)SEQ * IN_DIM) return;
    int token = (int)(idx4 / IN_DIM);
    float w0 = wts[token * 2 + 0];
    float w1 = wts[token * 2 + 1];
    float4 y0 = *(const float4*)&g_y[(size_t)(token * 2 + 0) * IN_DIM + (idx4 % IN_DIM)];
    float4 y1 = *(const float4*)&g_y[(size_t)(token * 2 + 1) * IN_DIM + (idx4 % IN_DIM)];
    float4 r;
    r.x = w0 * y0.x + w1 * y1.x;
    r.y = w0 * y0.y + w1 * y1.y;
    r.z = w0 * y0.z + w1 * y1.z;
    r.w = w0 * y0.w + w1 * y1.w;
    *(float4*)&out[idx4] = r;
}

// ---------------- launch ----------------
extern "C" void kernel_launch(void* const* d_in, const int* in_sizes, int n_in,
                              void* d_out, int out_size) {
    const float* inp   = (const float*)d_in[0];
    const float* wts   = (const float*)d_in[1];
    const float* up    = (const float*)d_in[2];
    const float* gate  = (const float*)d_in[3];
    const float* down  = (const float*)d_in[4];
    const int*   sel   = (const int*)d_in[5];
    float* out = (float*)d_out;

    k_init<<<64, 256>>>();
    k_count<<<NTOK / 256, 256>>>(sel);
    k_scan<<<1, 32>>>();
    k_scatter<<<NTOK / 256, 256>>>(sel);

    dim3 g1(PERM_MAX / BM, HID / BN, 2);
    k_gemm1<<<g1, NTHREADS>>>(inp, up, gate);

    k_act<<<2048, 256>>>();

    dim3 g2(PERM_MAX / BM, IN_DIM / BN);
    k_gemm2<<<g2, NTHREADS>>>(down);

    k_combine<<<(SEQ * IN_DIM / 4 + 255) / 256, 256>>>(wts, out);
}

// round 3
// speedup vs baseline: 2.3297x; 2.3297x over previous
#include <cuda_runtime.h>
#include <cuda_bf16.h>
#include <math.h>
#include <stdint.h>

#define SEQ 8192
#define IN_DIM 1024
#define HID 2048
#define NEXP 8
#define TOPK 2
#define NTOK (SEQ * TOPK)
#define BM 128
#define BN 128
#define BK 32
#define PERM_MAX (NTOK + NEXP * BM)  // 17408

// smem stage layout: rows padded to 40 bf16 (80B) for conflict-free ldmatrix
#define LDK 40
#define ARR_BYTES (128 * LDK * 2)    // 10240
#define AH_OFF 0
#define AL_OFF (ARR_BYTES)
#define BH_OFF (2 * ARR_BYTES)
#define BL_OFF (3 * ARR_BYTES)
#define STG_BYTES (4 * ARR_BYTES)    // 40960
#define NSTAGE 3
#define SMEM_TOT (NSTAGE * STG_BYTES)

// ---------------- static device scratch ----------------
__device__ int g_count[NEXP];
__device__ int g_fill[NEXP];
__device__ int g_pbase[NEXP + 1];
__device__ int g_perm[PERM_MAX];

__device__ __nv_bfloat16 g_up_hi[(size_t)NEXP * HID * IN_DIM];
__device__ __nv_bfloat16 g_up_lo[(size_t)NEXP * HID * IN_DIM];
__device__ __nv_bfloat16 g_gt_hi[(size_t)NEXP * HID * IN_DIM];
__device__ __nv_bfloat16 g_gt_lo[(size_t)NEXP * HID * IN_DIM];
__device__ __nv_bfloat16 g_dn_hi[(size_t)NEXP * IN_DIM * HID];  // transposed [e][n][k]
__device__ __nv_bfloat16 g_dn_lo[(size_t)NEXP * IN_DIM * HID];
__device__ __nv_bfloat16 g_in_hi[(size_t)SEQ * IN_DIM];
__device__ __nv_bfloat16 g_in_lo[(size_t)SEQ * IN_DIM];
__device__ float g_hid[(size_t)PERM_MAX * HID];
__device__ float g_gat[(size_t)PERM_MAX * HID];
__device__ __nv_bfloat16 g_act_hi[(size_t)PERM_MAX * HID];
__device__ __nv_bfloat16 g_act_lo[(size_t)PERM_MAX * HID];
__device__ float g_y[(size_t)NTOK * IN_DIM];

// ---------------- helpers ----------------
__device__ __forceinline__ uint32_t smem_u32(const void* p) {
    uint32_t a;
    asm("{ .reg .u64 t; cvta.to.shared.u64 t, %1; cvt.u32.u64 %0, t; }" : "=r"(a) : "l"(p));
    return a;
}
__device__ __forceinline__ void cp16(uint32_t dst, const void* src, int sz) {
    asm volatile("cp.async.cg.shared.global [%0], [%1], 16, %2;" :: "r"(dst), "l"(src), "r"(sz) : "memory");
}
__device__ __forceinline__ void cp_commit() { asm volatile("cp.async.commit_group;" ::: "memory"); }
__device__ __forceinline__ void cp_wait1() { asm volatile("cp.async.wait_group 1;" ::: "memory"); }

__device__ __forceinline__ void ldm4(uint32_t* r, uint32_t a) {
    asm volatile("ldmatrix.sync.aligned.m8n8.x4.shared.b16 {%0,%1,%2,%3},[%4];"
                 : "=r"(r[0]), "=r"(r[1]), "=r"(r[2]), "=r"(r[3]) : "r"(a));
}
__device__ __forceinline__ void ldm2(uint32_t* r, uint32_t a) {
    asm volatile("ldmatrix.sync.aligned.m8n8.x2.shared.b16 {%0,%1},[%2];"
                 : "=r"(r[0]), "=r"(r[1]) : "r"(a));
}
__device__ __forceinline__ void mma16816(float* c, const uint32_t* a, const uint32_t* b) {
    asm volatile("mma.sync.aligned.m16n8k16.row.col.f32.bf16.bf16.f32 "
                 "{%0,%1,%2,%3},{%4,%5,%6,%7},{%8,%9},{%0,%1,%2,%3};"
                 : "+f"(c[0]), "+f"(c[1]), "+f"(c[2]), "+f"(c[3])
                 : "r"(a[0]), "r"(a[1]), "r"(a[2]), "r"(a[3]), "r"(b[0]), "r"(b[1]));
}
__device__ __forceinline__ float gelu_tanh(float x) {
    float x3 = x * x * x;
    return 0.5f * x * (1.f + tanhf(0.7978845608028654f * (x + 0.044715f * x3)));
}

// ---------------- routing ----------------
__global__ void k_init() {
    int i = blockIdx.x * blockDim.x + threadIdx.x;
    if (i < NEXP) { g_count[i] = 0; g_fill[i] = 0; }
    for (int j = i; j < PERM_MAX; j += gridDim.x * blockDim.x) g_perm[j] = -1;
}
__global__ void k_count(const int* __restrict__ sel) {
    int s = blockIdx.x * blockDim.x + threadIdx.x;
    if (s < NTOK) atomicAdd(&g_count[sel[s]], 1);
}
__global__ void k_scan() {
    if (threadIdx.x == 0) {
        int acc = 0;
        g_pbase[0] = 0;
        for (int e = 0; e < NEXP; e++) {
            acc += ((g_count[e] + BM - 1) / BM) * BM;
            g_pbase[e + 1] = acc;
        }
    }
}
__global__ void k_scatter(const int* __restrict__ sel) {
    int s = blockIdx.x * blockDim.x + threadIdx.x;
    if (s < NTOK) {
        int e = sel[s];
        int pos = g_pbase[e] + atomicAdd(&g_fill[e], 1);
        g_perm[pos] = s;
    }
}

// ---------------- fp32 -> bf16 hi/lo split ----------------
__global__ void k_cvt(const float* __restrict__ src, int n4, int which) {
    __nv_bfloat16 *hi, *lo;
    if (which == 0)      { hi = g_up_hi; lo = g_up_lo; }
    else if (which == 1) { hi = g_gt_hi; lo = g_gt_lo; }
    else                 { hi = g_in_hi; lo = g_in_lo; }
    for (int i = blockIdx.x * blockDim.x + threadIdx.x; i < n4; i += gridDim.x * blockDim.x) {
        float4 v = ((const float4*)src)[i];
        __nv_bfloat16 h0 = __float2bfloat16(v.x), h1 = __float2bfloat16(v.y);
        __nv_bfloat16 h2 = __float2bfloat16(v.z), h3 = __float2bfloat16(v.w);
        __nv_bfloat162* H = (__nv_bfloat162*)(hi) + 2 * (size_t)i;
        __nv_bfloat162* L = (__nv_bfloat162*)(lo) + 2 * (size_t)i;
        H[0] = __halves2bfloat162(h0, h1);
        H[1] = __halves2bfloat162(h2, h3);
        L[0] = __halves2bfloat162(__float2bfloat16(v.x - __bfloat162float(h0)),
                                  __float2bfloat16(v.y - __bfloat162float(h1)));
        L[1] = __halves2bfloat162(__float2bfloat16(v.z - __bfloat162float(h2)),
                                  __float2bfloat16(v.w - __bfloat162float(h3)));
    }
}

// down [e][k(HID)][n(IN_DIM)] -> g_dn [e][n][k] bf16 hi/lo
__global__ void k_cvt_dnT(const float* __restrict__ down) {
    __shared__ float t[32][33];
    int e = blockIdx.z;
    int n0 = blockIdx.x * 32, k0 = blockIdx.y * 32;
    for (int i = threadIdx.y; i < 32; i += 8)
        t[i][threadIdx.x] = down[((size_t)e * HID + k0 + i) * IN_DIM + n0 + threadIdx.x];
    __syncthreads();
    for (int i = threadIdx.y; i < 32; i += 8) {
        float v = t[threadIdx.x][i];
        __nv_bfloat16 h = __float2bfloat16(v);
        size_t o = ((size_t)e * IN_DIM + n0 + i) * HID + k0 + threadIdx.x;
        g_dn_hi[o] = h;
        g_dn_lo[o] = __float2bfloat16(v - __bfloat162float(h));
    }
}

// ---------------- GEMM1: gathered x @ W^T (up or gate), fp32 out ----------------
__global__ __launch_bounds__(256, 1) void k_gemm1() {
    int row0 = blockIdx.x * BM;
    if (row0 >= g_pbase[NEXP]) return;
    int nblk = blockIdx.y, which = blockIdx.z;

    extern __shared__ char sm[];
    __shared__ int s_tok[BM];
    int tid = threadIdx.x, lane = tid & 31, wid = tid >> 5;

    int e = 0;
    while (row0 >= g_pbase[e + 1]) e++;
    if (tid < BM) {
        int s = g_perm[row0 + tid];
        s_tok[tid] = (s >= 0) ? (s >> 1) : -1;
    }
    __syncthreads();

    size_t wof = ((size_t)e * HID + (size_t)nblk * BN) * IN_DIM;
    const __nv_bfloat16* Wh = (which ? g_gt_hi : g_up_hi) + wof;
    const __nv_bfloat16* Wl = (which ? g_gt_lo : g_up_lo) + wof;
    uint32_t sb = smem_u32(sm);

    auto load_stage = [&](int st, int k0) {
        uint32_t base = sb + (uint32_t)st * STG_BYTES;
        #pragma unroll
        for (int i = 0; i < 2; i++) {
            int idx = tid + i * 256;
            int r = idx >> 2, c = idx & 3;
            int tok = s_tok[r];
            size_t so = (size_t)(tok < 0 ? 0 : tok) * IN_DIM + k0 + c * 8;
            uint32_t d = base + (uint32_t)(r * LDK + c * 8) * 2;
            int sz = tok < 0 ? 0 : 16;
            cp16(d + AH_OFF, g_in_hi + so, sz);
            cp16(d + AL_OFF, g_in_lo + so, sz);
        }
        #pragma unroll
        for (int i = 0; i < 2; i++) {
            int idx = tid + i * 256;
            int r = idx >> 2, c = idx & 3;
            size_t so = (size_t)r * IN_DIM + k0 + c * 8;
            uint32_t d = base + (uint32_t)(r * LDK + c * 8) * 2;
            cp16(d + BH_OFF, Wh + so, 16);
            cp16(d + BL_OFF, Wl + so, 16);
        }
        cp_commit();
    };

    int wm = (wid & 1) * 64, wn = (wid >> 1) * 32;
    float acc[4][4][4];
    #pragma unroll
    for (int a = 0; a < 4; a++)
        #pragma unroll
        for (int b = 0; b < 4; b++)
            #pragma unroll
            for (int c = 0; c < 4; c++) acc[a][b][c] = 0.f;

    load_stage(0, 0);
    load_stage(1, BK);

    const int NS = IN_DIM / BK;  // 32
    for (int s = 0; s < NS; s++) {
        cp_wait1();
        __syncthreads();
        if (s + 2 < NS) load_stage((s + 2) % NSTAGE, (s + 2) * BK);
        else cp_commit();

        uint32_t base = sb + (uint32_t)(s % NSTAGE) * STG_BYTES;
        #pragma unroll
        for (int kh = 0; kh < 2; kh++) {
            uint32_t bh[4][2], bl[4][2];
            #pragma unroll
            for (int nt = 0; nt < 4; nt++) {
                uint32_t brow = wn + nt * 8 + (lane & 7);
                uint32_t bcol = kh * 16 + 8 * ((lane & 15) >> 3);
                uint32_t off = (brow * LDK + bcol) * 2;
                ldm2(bh[nt], base + BH_OFF + off);
                ldm2(bl[nt], base + BL_OFF + off);
            }
            #pragma unroll
            for (int mt = 0; mt < 4; mt++) {
                uint32_t arow = wm + mt * 16 + (lane & 15);
                uint32_t acol = kh * 16 + 8 * (lane >> 4);
                uint32_t off = (arow * LDK + acol) * 2;
                uint32_t ah[4], al[4];
                ldm4(ah, base + AH_OFF + off);
                ldm4(al, base + AL_OFF + off);
                #pragma unroll
                for (int nt = 0; nt < 4; nt++) {
                    mma16816(acc[mt][nt], ah, bh[nt]);
                    mma16816(acc[mt][nt], ah, bl[nt]);
                    mma16816(acc[mt][nt], al, bh[nt]);
                }
            }
        }
    }

    float* Out = which ? g_gat : g_hid;
    #pragma unroll
    for (int mt = 0; mt < 4; mt++) {
        int gr = row0 + wm + mt * 16 + (lane >> 2);
        #pragma unroll
        for (int nt = 0; nt < 4; nt++) {
            int gc = nblk * BN + wn + nt * 8 + (lane & 3) * 2;
            *(float2*)&Out[(size_t)gr * HID + gc]       = make_float2(acc[mt][nt][0], acc[mt][nt][1]);
            *(float2*)&Out[(size_t)(gr + 8) * HID + gc] = make_float2(acc[mt][nt][2], acc[mt][nt][3]);
        }
    }
}

// ---------------- act: gelu(g)*h -> bf16 hi/lo ----------------
__global__ void k_act() {
    size_t total = (size_t)g_pbase[NEXP] * HID;
    size_t stride = (size_t)gridDim.x * blockDim.x * 4;
    for (size_t idx = ((size_t)blockIdx.x * blockDim.x + threadIdx.x) * 4;
         idx < total; idx += stride) {
        float4 g = *(float4*)&g_gat[idx];
        float4 h = *(float4*)&g_hid[idx];
        float a0 = gelu_tanh(g.x) * h.x;
        float a1 = gelu_tanh(g.y) * h.y;
        float a2 = gelu_tanh(g.z) * h.z;
        float a3 = gelu_tanh(g.w) * h.w;
        __nv_bfloat16 b0 = __float2bfloat16(a0), b1 = __float2bfloat16(a1);
        __nv_bfloat16 b2 = __float2bfloat16(a2), b3 = __float2bfloat16(a3);
        __nv_bfloat162 hp0 = __halves2bfloat162(b0, b1);
        __nv_bfloat162 hp1 = __halves2bfloat162(b2, b3);
        __nv_bfloat162 lp0 = __halves2bfloat162(__float2bfloat16(a0 - __bfloat162float(b0)),
                                                __float2bfloat16(a1 - __bfloat162float(b1)));
        __nv_bfloat162 lp1 = __halves2bfloat162(__float2bfloat16(a2 - __bfloat162float(b2)),
                                                __float2bfloat16(a3 - __bfloat162float(b3)));
        *(uint2*)&g_act_hi[idx] = make_uint2(*(uint32_t*)&hp0, *(uint32_t*)&hp1);
        *(uint2*)&g_act_lo[idx] = make_uint2(*(uint32_t*)&lp0, *(uint32_t*)&lp1);
    }
}

// ---------------- GEMM2: act @ downT, scatter to g_y ----------------
__global__ __launch_bounds__(256, 1) void k_gemm2() {
    int row0 = blockIdx.x * BM;
    if (row0 >= g_pbase[NEXP]) return;
    int nblk = blockIdx.y;

    extern __shared__ char sm[];
    __shared__ int s_slot[BM];
    int tid = threadIdx.x, lane = tid & 31, wid = tid >> 5;

    int e = 0;
    while (row0 >= g_pbase[e + 1]) e++;
    if (tid < BM) s_slot[tid] = g_perm[row0 + tid];
    __syncthreads();

    size_t wof = ((size_t)e * IN_DIM + (size_t)nblk * BN) * HID;
    const __nv_bfloat16* Wh = g_dn_hi + wof;
    const __nv_bfloat16* Wl = g_dn_lo + wof;
    uint32_t sb = smem_u32(sm);

    auto load_stage = [&](int st, int k0) {
        uint32_t base = sb + (uint32_t)st * STG_BYTES;
        #pragma unroll
        for (int i = 0; i < 2; i++) {
            int idx = tid + i * 256;
            int r = idx >> 2, c = idx & 3;
            size_t so = (size_t)(row0 + r) * HID + k0 + c * 8;
            uint32_t d = base + (uint32_t)(r * LDK + c * 8) * 2;
            cp16(d + AH_OFF, g_act_hi + so, 16);
            cp16(d + AL_OFF, g_act_lo + so, 16);
        }
        #pragma unroll
        for (int i = 0; i < 2; i++) {
            int idx = tid + i * 256;
            int r = idx >> 2, c = idx & 3;
            size_t so = (size_t)r * HID + k0 + c * 8;
            uint32_t d = base + (uint32_t)(r * LDK + c * 8) * 2;
            cp16(d + BH_OFF, Wh + so, 16);
            cp16(d + BL_OFF, Wl + so, 16);
        }
        cp_commit();
    };

    int wm = (wid & 1) * 64, wn = (wid >> 1) * 32;
    float acc[4][4][4];
    #pragma unroll
    for (int a = 0; a < 4; a++)
        #pragma unroll
        for (int b = 0; b < 4; b++)
            #pragma unroll
            for (int c = 0; c < 4; c++) acc[a][b][c] = 0.f;

    load_stage(0, 0);
    load_stage(1, BK);

    const int NS = HID / BK;  // 64
    for (int s = 0; s < NS; s++) {
        cp_wait1();
        __syncthreads();
        if (s + 2 < NS) load_stage((s + 2) % NSTAGE, (s + 2) * BK);
        else cp_commit();

        uint32_t base = sb + (uint32_t)(s % NSTAGE) * STG_BYTES;
        #pragma unroll
        for (int kh = 0; kh < 2; kh++) {
            uint32_t bh[4][2], bl[4][2];
            #pragma unroll
            for (int nt = 0; nt < 4; nt++) {
                uint32_t brow = wn + nt * 8 + (lane & 7);
                uint32_t bcol = kh * 16 + 8 * ((lane & 15) >> 3);
                uint32_t off = (brow * LDK + bcol) * 2;
                ldm2(bh[nt], base + BH_OFF + off);
                ldm2(bl[nt], base + BL_OFF + off);
            }
            #pragma unroll
            for (int mt = 0; mt < 4; mt++) {
                uint32_t arow = wm + mt * 16 + (lane & 15);
                uint32_t acol = kh * 16 + 8 * (lane >> 4);
                uint32_t off = (arow * LDK + acol) * 2;
                uint32_t ah[4], al[4];
                ldm4(ah, base + AH_OFF + off);
                ldm4(al, base + AL_OFF + off);
                #pragma unroll
                for (int nt = 0; nt < 4; nt++) {
                    mma16816(acc[mt][nt], ah, bh[nt]);
                    mma16816(acc[mt][nt], ah, bl[nt]);
                    mma16816(acc[mt][nt], al, bh[nt]);
                }
            }
        }
    }

    #pragma unroll
    for (int mt = 0; mt < 4; mt++) {
        int lr = wm + mt * 16 + (lane >> 2);
        int s0 = s_slot[lr];
        int s1 = s_slot[lr + 8];
        #pragma unroll
        for (int nt = 0; nt < 4; nt++) {
            int gc = nblk * BN + wn + nt * 8 + (lane & 3) * 2;
            if (s0 >= 0)
                *(float2*)&g_y[(size_t)s0 * IN_DIM + gc] = make_float2(acc[mt][nt][0], acc[mt][nt][1]);
            if (s1 >= 0)
                *(float2*)&g_y[(size_t)s1 * IN_DIM + gc] = make_float2(acc[mt][nt][2], acc[mt][nt][3]);
        }
    }
}

// ---------------- combine ----------------
__global__ void k_combine(const float* __restrict__ wts, float* __restrict__ out) {
    size_t idx4 = ((size_t)blockIdx.x * blockDim.x + threadIdx.x) * 4;
    if (idx4 >= (size_t)SEQ * IN_DIM) return;
    int token = (int)(idx4 / IN_DIM);
    int col = (int)(idx4 % IN_DIM);
    float w0 = wts[token * 2 + 0];
    float w1 = wts[token * 2 + 1];
    float4 y0 = *(const float4*)&g_y[(size_t)(token * 2 + 0) * IN_DIM + col];
    float4 y1 = *(const float4*)&g_y[(size_t)(token * 2 + 1) * IN_DIM + col];
    float4 r;
    r.x = w0 * y0.x + w1 * y1.x;
    r.y = w0 * y0.y + w1 * y1.y;
    r.z = w0 * y0.z + w1 * y1.z;
    r.w = w0 * y0.w + w1 * y1.w;
    *(float4*)&out[idx4] = r;
}

// ---------------- launch ----------------
extern "C" void kernel_launch(void* const* d_in, const int* in_sizes, int n_in,
                              void* d_out, int out_size) {
    const float* inp  = (const float*)d_in[0];
    const float* wts  = (const float*)d_in[1];
    const float* up   = (const float*)d_in[2];
    const float* gate = (const float*)d_in[3];
    const float* down = (const float*)d_in[4];
    const int*   sel  = (const int*)d_in[5];
    float* out = (float*)d_out;

    cudaFuncSetAttribute(k_gemm1, cudaFuncAttributeMaxDynamicSharedMemorySize, SMEM_TOT);
    cudaFuncSetAttribute(k_gemm2, cudaFuncAttributeMaxDynamicSharedMemorySize, SMEM_TOT);

    k_init<<<64, 256>>>();
    k_count<<<NTOK / 256, 256>>>(sel);
    k_scan<<<1, 32>>>();
    k_scatter<<<NTOK / 256, 256>>>(sel);

    k_cvt<<<4096, 256>>>(up,   (int)((size_t)NEXP * HID * IN_DIM / 4), 0);
    k_cvt<<<4096, 256>>>(gate, (int)((size_t)NEXP * HID * IN_DIM / 4), 1);
    k_cvt<<<2048, 256>>>(inp,  SEQ * IN_DIM / 4, 2);
    k_cvt_dnT<<<dim3(IN_DIM / 32, HID / 32, NEXP), dim3(32, 8)>>>(down);

    k_gemm1<<<dim3(PERM_MAX / BM, HID / BN, 2), 256, SMEM_TOT>>>();
    k_act<<<2048, 256>>>();
    k_gemm2<<<dim3(PERM_MAX / BM, IN_DIM / BN), 256, SMEM_TOT>>>();
    k_combine<<<(SEQ * IN_DIM / 4 + 255) / 256, 256>>>(wts, out);
}

// round 4
// speedup vs baseline: 2.5658x; 1.1013x over previous
#include <cuda_runtime.h>
#include <cuda_bf16.h>
#include <math.h>
#include <stdint.h>

#define SEQ 8192
#define IN_DIM 1024
#define HID 2048
#define NEXP 8
#define TOPK 2
#define NTOK (SEQ * TOPK)
#define BM 128
#define BK 32
#define PERM_MAX (NTOK + NEXP * BM)  // 17408

// smem rows padded to 40 bf16 (80B) for conflict-free ldmatrix
#define LDK 40
#define ARR_BYTES (128 * LDK * 2)    // 10240 (128 rows)
#define ARR2_BYTES (256 * LDK * 2)   // 20480 (256 rows)

// GEMM1 fused stage: AH AL UH UL GH GL
#define S1_AH 0
#define S1_AL (ARR_BYTES)
#define S1_UH (2 * ARR_BYTES)
#define S1_UL (3 * ARR_BYTES)
#define S1_GH (4 * ARR_BYTES)
#define S1_GL (5 * ARR_BYTES)
#define STG1 (6 * ARR_BYTES)         // 61440
// GEMM2 stage: AH AL BH(256) BL(256)
#define S2_AH 0
#define S2_AL (ARR_BYTES)
#define S2_BH (2 * ARR_BYTES)
#define S2_BL (2 * ARR_BYTES + ARR2_BYTES)
#define STG2 (2 * ARR_BYTES + 2 * ARR2_BYTES)  // 61440
#define NSTAGE 3
#define SMEM_TOT (NSTAGE * STG1)     // 184320

// ---------------- static device scratch ----------------
__device__ int g_count[NEXP];
__device__ int g_fill[NEXP];
__device__ int g_pbase[NEXP + 1];
__device__ int g_perm[PERM_MAX];

__device__ __nv_bfloat16 g_up_hi[(size_t)NEXP * HID * IN_DIM];
__device__ __nv_bfloat16 g_up_lo[(size_t)NEXP * HID * IN_DIM];
__device__ __nv_bfloat16 g_gt_hi[(size_t)NEXP * HID * IN_DIM];
__device__ __nv_bfloat16 g_gt_lo[(size_t)NEXP * HID * IN_DIM];
__device__ __nv_bfloat16 g_dn_hi[(size_t)NEXP * IN_DIM * HID];  // transposed [e][n][k]
__device__ __nv_bfloat16 g_dn_lo[(size_t)NEXP * IN_DIM * HID];
__device__ __nv_bfloat16 g_in_hi[(size_t)SEQ * IN_DIM];
__device__ __nv_bfloat16 g_in_lo[(size_t)SEQ * IN_DIM];
__device__ __nv_bfloat16 g_act_hi[(size_t)PERM_MAX * HID];
__device__ __nv_bfloat16 g_act_lo[(size_t)PERM_MAX * HID];
__device__ float g_y[(size_t)NTOK * IN_DIM];

// ---------------- helpers ----------------
__device__ __forceinline__ uint32_t smem_u32(const void* p) {
    uint32_t a;
    asm("{ .reg .u64 t; cvta.to.shared.u64 t, %1; cvt.u32.u64 %0, t; }" : "=r"(a) : "l"(p));
    return a;
}
__device__ __forceinline__ void cp16(uint32_t dst, const void* src, int sz) {
    asm volatile("cp.async.cg.shared.global [%0], [%1], 16, %2;" :: "r"(dst), "l"(src), "r"(sz) : "memory");
}
__device__ __forceinline__ void cp_commit() { asm volatile("cp.async.commit_group;" ::: "memory"); }
__device__ __forceinline__ void cp_wait1() { asm volatile("cp.async.wait_group 1;" ::: "memory"); }

__device__ __forceinline__ void ldm4(uint32_t* r, uint32_t a) {
    asm volatile("ldmatrix.sync.aligned.m8n8.x4.shared.b16 {%0,%1,%2,%3},[%4];"
                 : "=r"(r[0]), "=r"(r[1]), "=r"(r[2]), "=r"(r[3]) : "r"(a));
}
__device__ __forceinline__ void ldm2(uint32_t* r, uint32_t a) {
    asm volatile("ldmatrix.sync.aligned.m8n8.x2.shared.b16 {%0,%1},[%2];"
                 : "=r"(r[0]), "=r"(r[1]) : "r"(a));
}
__device__ __forceinline__ void mma16816(float* c, const uint32_t* a, const uint32_t* b) {
    asm volatile("mma.sync.aligned.m16n8k16.row.col.f32.bf16.bf16.f32 "
                 "{%0,%1,%2,%3},{%4,%5,%6,%7},{%8,%9},{%0,%1,%2,%3};"
                 : "+f"(c[0]), "+f"(c[1]), "+f"(c[2]), "+f"(c[3])
                 : "r"(a[0]), "r"(a[1]), "r"(a[2]), "r"(a[3]), "r"(b[0]), "r"(b[1]));
}
__device__ __forceinline__ float gelu_tanh(float x) {
    float x3 = x * x * x;
    return 0.5f * x * (1.f + tanhf(0.7978845608028654f * (x + 0.044715f * x3)));
}

// ---------------- routing ----------------
__global__ void k_init() {
    int i = blockIdx.x * blockDim.x + threadIdx.x;
    if (i < NEXP) { g_count[i] = 0; g_fill[i] = 0; }
    for (int j = i; j < PERM_MAX; j += gridDim.x * blockDim.x) g_perm[j] = -1;
}
__global__ void k_count(const int* __restrict__ sel) {
    int s = blockIdx.x * blockDim.x + threadIdx.x;
    if (s < NTOK) atomicAdd(&g_count[sel[s]], 1);
}
__global__ void k_scan() {
    if (threadIdx.x == 0) {
        int acc = 0;
        g_pbase[0] = 0;
        for (int e = 0; e < NEXP; e++) {
            acc += ((g_count[e] + BM - 1) / BM) * BM;
            g_pbase[e + 1] = acc;
        }
    }
}
__global__ void k_scatter(const int* __restrict__ sel) {
    int s = blockIdx.x * blockDim.x + threadIdx.x;
    if (s < NTOK) {
        int e = sel[s];
        int pos = g_pbase[e] + atomicAdd(&g_fill[e], 1);
        g_perm[pos] = s;
    }
}

// ---------------- fp32 -> bf16 hi/lo split ----------------
__global__ void k_cvt(const float* __restrict__ src, int n4, int which) {
    __nv_bfloat16 *hi, *lo;
    if (which == 0)      { hi = g_up_hi; lo = g_up_lo; }
    else if (which == 1) { hi = g_gt_hi; lo = g_gt_lo; }
    else                 { hi = g_in_hi; lo = g_in_lo; }
    for (int i = blockIdx.x * blockDim.x + threadIdx.x; i < n4; i += gridDim.x * blockDim.x) {
        float4 v = ((const float4*)src)[i];
        __nv_bfloat16 h0 = __float2bfloat16(v.x), h1 = __float2bfloat16(v.y);
        __nv_bfloat16 h2 = __float2bfloat16(v.z), h3 = __float2bfloat16(v.w);
        __nv_bfloat162* H = (__nv_bfloat162*)(hi) + 2 * (size_t)i;
        __nv_bfloat162* L = (__nv_bfloat162*)(lo) + 2 * (size_t)i;
        H[0] = __halves2bfloat162(h0, h1);
        H[1] = __halves2bfloat162(h2, h3);
        L[0] = __halves2bfloat162(__float2bfloat16(v.x - __bfloat162float(h0)),
                                  __float2bfloat16(v.y - __bfloat162float(h1)));
        L[1] = __halves2bfloat162(__float2bfloat16(v.z - __bfloat162float(h2)),
                                  __float2bfloat16(v.w - __bfloat162float(h3)));
    }
}

// down [e][k(HID)][n(IN_DIM)] -> g_dn [e][n][k] bf16 hi/lo
__global__ void k_cvt_dnT(const float* __restrict__ down) {
    __shared__ float t[32][33];
    int e = blockIdx.z;
    int n0 = blockIdx.x * 32, k0 = blockIdx.y * 32;
    for (int i = threadIdx.y; i < 32; i += 8)
        t[i][threadIdx.x] = down[((size_t)e * HID + k0 + i) * IN_DIM + n0 + threadIdx.x];
    __syncthreads();
    for (int i = threadIdx.y; i < 32; i += 8) {
        float v = t[threadIdx.x][i];
        __nv_bfloat16 h = __float2bfloat16(v);
        size_t o = ((size_t)e * IN_DIM + n0 + i) * HID + k0 + threadIdx.x;
        g_dn_hi[o] = h;
        g_dn_lo[o] = __float2bfloat16(v - __bfloat162float(h));
    }
}

// ---------------- GEMM1 fused: x @ Wup^T and x @ Wgate^T, epilogue gelu*h -> act hi/lo ----------------
__global__ __launch_bounds__(256, 1) void k_gemm1() {
    int row0 = blockIdx.x * BM;
    if (row0 >= g_pbase[NEXP]) return;
    int nblk = blockIdx.y;

    extern __shared__ char sm[];
    __shared__ int s_tok[BM];
    int tid = threadIdx.x, lane = tid & 31, wid = tid >> 5;

    int e = 0;
    while (row0 >= g_pbase[e + 1]) e++;
    if (tid < BM) {
        int s = g_perm[row0 + tid];
        s_tok[tid] = (s >= 0) ? (s >> 1) : -1;
    }
    __syncthreads();

    size_t wof = ((size_t)e * HID + (size_t)nblk * 128) * IN_DIM;
    const __nv_bfloat16* Uh = g_up_hi + wof;
    const __nv_bfloat16* Ul = g_up_lo + wof;
    const __nv_bfloat16* Gh = g_gt_hi + wof;
    const __nv_bfloat16* Gl = g_gt_lo + wof;
    uint32_t sb = smem_u32(sm);

    auto load_stage = [&](int st, int k0) {
        uint32_t base = sb + (uint32_t)st * STG1;
        #pragma unroll
        for (int i = 0; i < 2; i++) {
            int idx = tid + i * 256;
            int r = idx >> 2, c = idx & 3;
            uint32_t d = base + (uint32_t)(r * LDK + c * 8) * 2;
            int tok = s_tok[r];
            size_t ao = (size_t)(tok < 0 ? 0 : tok) * IN_DIM + k0 + c * 8;
            int sz = tok < 0 ? 0 : 16;
            cp16(d + S1_AH, g_in_hi + ao, sz);
            cp16(d + S1_AL, g_in_lo + ao, sz);
            size_t so = (size_t)r * IN_DIM + k0 + c * 8;
            cp16(d + S1_UH, Uh + so, 16);
            cp16(d + S1_UL, Ul + so, 16);
            cp16(d + S1_GH, Gh + so, 16);
            cp16(d + S1_GL, Gl + so, 16);
        }
        cp_commit();
    };

    int wm = (wid & 1) * 64, wn = (wid >> 1) * 32;
    float acc_u[4][4][4], acc_g[4][4][4];
    #pragma unroll
    for (int a = 0; a < 4; a++)
        #pragma unroll
        for (int b = 0; b < 4; b++)
            #pragma unroll
            for (int c = 0; c < 4; c++) { acc_u[a][b][c] = 0.f; acc_g[a][b][c] = 0.f; }

    load_stage(0, 0);
    load_stage(1, BK);

    const int NS = IN_DIM / BK;  // 32
    for (int s = 0; s < NS; s++) {
        cp_wait1();
        __syncthreads();
        if (s + 2 < NS) load_stage((s + 2) % NSTAGE, (s + 2) * BK);
        else cp_commit();

        uint32_t base = sb + (uint32_t)(s % NSTAGE) * STG1;
        #pragma unroll
        for (int kh = 0; kh < 2; kh++) {
            uint32_t ubh[4][2], ubl[4][2], gbh[4][2], gbl[4][2];
            #pragma unroll
            for (int nt = 0; nt < 4; nt++) {
                uint32_t brow = wn + nt * 8 + (lane & 7);
                uint32_t bcol = kh * 16 + 8 * ((lane & 15) >> 3);
                uint32_t off = (brow * LDK + bcol) * 2;
                ldm2(ubh[nt], base + S1_UH + off);
                ldm2(ubl[nt], base + S1_UL + off);
                ldm2(gbh[nt], base + S1_GH + off);
                ldm2(gbl[nt], base + S1_GL + off);
            }
            #pragma unroll
            for (int mt = 0; mt < 4; mt++) {
                uint32_t arow = wm + mt * 16 + (lane & 15);
                uint32_t acol = kh * 16 + 8 * (lane >> 4);
                uint32_t off = (arow * LDK + acol) * 2;
                uint32_t ah[4], al[4];
                ldm4(ah, base + S1_AH + off);
                ldm4(al, base + S1_AL + off);
                #pragma unroll
                for (int nt = 0; nt < 4; nt++) {
                    mma16816(acc_u[mt][nt], ah, ubh[nt]);
                    mma16816(acc_u[mt][nt], ah, ubl[nt]);
                    mma16816(acc_u[mt][nt], al, ubh[nt]);
                    mma16816(acc_g[mt][nt], ah, gbh[nt]);
                    mma16816(acc_g[mt][nt], ah, gbl[nt]);
                    mma16816(acc_g[mt][nt], al, gbh[nt]);
                }
            }
        }
    }

    // epilogue: act = gelu(g) * h, split into bf16 hi/lo
    #pragma unroll
    for (int mt = 0; mt < 4; mt++) {
        int gr = row0 + wm + mt * 16 + (lane >> 2);
        #pragma unroll
        for (int nt = 0; nt < 4; nt++) {
            int gc = nblk * 128 + wn + nt * 8 + (lane & 3) * 2;
            #pragma unroll
            for (int half = 0; half < 2; half++) {
                float a0 = gelu_tanh(acc_g[mt][nt][2 * half])     * acc_u[mt][nt][2 * half];
                float a1 = gelu_tanh(acc_g[mt][nt][2 * half + 1]) * acc_u[mt][nt][2 * half + 1];
                __nv_bfloat16 b0 = __float2bfloat16(a0), b1 = __float2bfloat16(a1);
                __nv_bfloat162 hp = __halves2bfloat162(b0, b1);
                __nv_bfloat162 lp = __halves2bfloat162(__float2bfloat16(a0 - __bfloat162float(b0)),
                                                       __float2bfloat16(a1 - __bfloat162float(b1)));
                size_t o = (size_t)(gr + 8 * half) * HID + gc;
                *(uint32_t*)&g_act_hi[o] = *(uint32_t*)&hp;
                *(uint32_t*)&g_act_lo[o] = *(uint32_t*)&lp;
            }
        }
    }
}

// ---------------- GEMM2: act @ downT (BN=256), scatter to g_y ----------------
__global__ __launch_bounds__(256, 1) void k_gemm2() {
    int row0 = blockIdx.x * BM;
    if (row0 >= g_pbase[NEXP]) return;
    int nblk = blockIdx.y;

    extern __shared__ char sm[];
    __shared__ int s_slot[BM];
    int tid = threadIdx.x, lane = tid & 31, wid = tid >> 5;

    int e = 0;
    while (row0 >= g_pbase[e + 1]) e++;
    if (tid < BM) s_slot[tid] = g_perm[row0 + tid];
    __syncthreads();

    size_t wof = ((size_t)e * IN_DIM + (size_t)nblk * 256) * HID;
    const __nv_bfloat16* Wh = g_dn_hi + wof;
    const __nv_bfloat16* Wl = g_dn_lo + wof;
    uint32_t sb = smem_u32(sm);

    auto load_stage = [&](int st, int k0) {
        uint32_t base = sb + (uint32_t)st * STG2;
        #pragma unroll
        for (int i = 0; i < 2; i++) {
            int idx = tid + i * 256;
            int r = idx >> 2, c = idx & 3;
            uint32_t d = base + (uint32_t)(r * LDK + c * 8) * 2;
            size_t ao = (size_t)(row0 + r) * HID + k0 + c * 8;
            cp16(d + S2_AH, g_act_hi + ao, 16);
            cp16(d + S2_AL, g_act_lo + ao, 16);
        }
        #pragma unroll
        for (int i = 0; i < 4; i++) {
            int idx = tid + i * 256;
            int r = idx >> 2, c = idx & 3;   // r 0..255
            uint32_t d = base + (uint32_t)(r * LDK + c * 8) * 2;
            size_t so = (size_t)r * HID + k0 + c * 8;
            cp16(d + S2_BH, Wh + so, 16);
            cp16(d + S2_BL, Wl + so, 16);
        }
        cp_commit();
    };

    int wm = (wid & 1) * 64, wn = (wid >> 1) * 64;
    float acc[4][8][4];
    #pragma unroll
    for (int a = 0; a < 4; a++)
        #pragma unroll
        for (int b = 0; b < 8; b++)
            #pragma unroll
            for (int c = 0; c < 4; c++) acc[a][b][c] = 0.f;

    load_stage(0, 0);
    load_stage(1, BK);

    const int NS = HID / BK;  // 64
    for (int s = 0; s < NS; s++) {
        cp_wait1();
        __syncthreads();
        if (s + 2 < NS) load_stage((s + 2) % NSTAGE, (s + 2) * BK);
        else cp_commit();

        uint32_t base = sb + (uint32_t)(s % NSTAGE) * STG2;
        #pragma unroll
        for (int kh = 0; kh < 2; kh++) {
            uint32_t bh[8][2], bl[8][2];
            #pragma unroll
            for (int nt = 0; nt < 8; nt++) {
                uint32_t brow = wn + nt * 8 + (lane & 7);
                uint32_t bcol = kh * 16 + 8 * ((lane & 15) >> 3);
                uint32_t off = (brow * LDK + bcol) * 2;
                ldm2(bh[nt], base + S2_BH + off);
                ldm2(bl[nt], base + S2_BL + off);
            }
            #pragma unroll
            for (int mt = 0; mt < 4; mt++) {
                uint32_t arow = wm + mt * 16 + (lane & 15);
                uint32_t acol = kh * 16 + 8 * (lane >> 4);
                uint32_t off = (arow * LDK + acol) * 2;
                uint32_t ah[4], al[4];
                ldm4(ah, base + S2_AH + off);
                ldm4(al, base + S2_AL + off);
                #pragma unroll
                for (int nt = 0; nt < 8; nt++) {
                    mma16816(acc[mt][nt], ah, bh[nt]);
                    mma16816(acc[mt][nt], ah, bl[nt]);
                    mma16816(acc[mt][nt], al, bh[nt]);
                }
            }
        }
    }

    #pragma unroll
    for (int mt = 0; mt < 4; mt++) {
        int lr = wm + mt * 16 + (lane >> 2);
        int s0 = s_slot[lr];
        int s1 = s_slot[lr + 8];
        #pragma unroll
        for (int nt = 0; nt < 8; nt++) {
            int gc = nblk * 256 + wn + nt * 8 + (lane & 3) * 2;
            if (s0 >= 0)
                *(float2*)&g_y[(size_t)s0 * IN_DIM + gc] = make_float2(acc[mt][nt][0], acc[mt][nt][1]);
            if (s1 >= 0)
                *(float2*)&g_y[(size_t)s1 * IN_DIM + gc] = make_float2(acc[mt][nt][2], acc[mt][nt][3]);
        }
    }
}

// ---------------- combine ----------------
__global__ void k_combine(const float* __restrict__ wts, float* __restrict__ out) {
    size_t idx4 = ((size_t)blockIdx.x * blockDim.x + threadIdx.x) * 4;
    if (idx4 >= (size_t)SEQ * IN_DIM) return;
    int token = (int)(idx4 / IN_DIM);
    int col = (int)(idx4 % IN_DIM);
    float w0 = wts[token * 2 + 0];
    float w1 = wts[token * 2 + 1];
    float4 y0 = *(const float4*)&g_y[(size_t)(token * 2 + 0) * IN_DIM + col];
    float4 y1 = *(const float4*)&g_y[(size_t)(token * 2 + 1) * IN_DIM + col];
    float4 r;
    r.x = w0 * y0.x + w1 * y1.x;
    r.y = w0 * y0.y + w1 * y1.y;
    r.z = w0 * y0.z + w1 * y1.z;
    r.w = w0 * y0.w + w1 * y1.w;
    *(float4*)&out[idx4] = r;
}

// ---------------- launch ----------------
extern "C" void kernel_launch(void* const* d_in, const int* in_sizes, int n_in,
                              void* d_out, int out_size) {
    const float* inp  = (const float*)d_in[0];
    const float* wts  = (const float*)d_in[1];
    const float* up   = (const float*)d_in[2];
    const float* gate = (const float*)d_in[3];
    const float* down = (const float*)d_in[4];
    const int*   sel  = (const int*)d_in[5];
    float* out = (float*)d_out;

    cudaFuncSetAttribute(k_gemm1, cudaFuncAttributeMaxDynamicSharedMemorySize, SMEM_TOT);
    cudaFuncSetAttribute(k_gemm2, cudaFuncAttributeMaxDynamicSharedMemorySize, SMEM_TOT);

    k_init<<<64, 256>>>();
    k_count<<<NTOK / 256, 256>>>(sel);
    k_scan<<<1, 32>>>();
    k_scatter<<<NTOK / 256, 256>>>(sel);

    k_cvt<<<4096, 256>>>(up,   (int)((size_t)NEXP * HID * IN_DIM / 4), 0);
    k_cvt<<<4096, 256>>>(gate, (int)((size_t)NEXP * HID * IN_DIM / 4), 1);
    k_cvt<<<2048, 256>>>(inp,  SEQ * IN_DIM / 4, 2);
    k_cvt_dnT<<<dim3(IN_DIM / 32, HID / 32, NEXP), dim3(32, 8)>>>(down);

    k_gemm1<<<dim3(PERM_MAX / BM, HID / 128), 256, SMEM_TOT>>>();
    k_gemm2<<<dim3(PERM_MAX / BM, IN_DIM / 256), 256, SMEM_TOT>>>();
    k_combine<<<(SEQ * IN_DIM / 4 + 255) / 256, 256>>>(wts, out);
}

// round 5
// speedup vs baseline: 2.6008x; 1.0137x over previous
#include <cuda_runtime.h>
#include <cuda_bf16.h>
#include <math.h>
#include <stdint.h>

#define SEQ 8192
#define IN_DIM 1024
#define HID 2048
#define NEXP 8
#define TOPK 2
#define NTOK (SEQ * TOPK)
#define BM 128
#define BK 32
#define PERM_MAX (NTOK + NEXP * BM)  // 17408

// smem rows padded to 40 bf16 (80B) for conflict-free ldmatrix
#define LDK 40
#define ARR_BYTES (128 * LDK * 2)    // 10240 (128 rows)
#define ARR2_BYTES (256 * LDK * 2)   // 20480 (256 rows)

// GEMM1 fused stage: AH AL UH UL GH GL
#define S1_AH 0
#define S1_AL (ARR_BYTES)
#define S1_UH (2 * ARR_BYTES)
#define S1_UL (3 * ARR_BYTES)
#define S1_GH (4 * ARR_BYTES)
#define S1_GL (5 * ARR_BYTES)
#define STG1 (6 * ARR_BYTES)         // 61440
// GEMM2 stage: AH AL BH(256) BL(256)
#define S2_AH 0
#define S2_AL (ARR_BYTES)
#define S2_BH (2 * ARR_BYTES)
#define S2_BL (2 * ARR_BYTES + ARR2_BYTES)
#define STG2 (2 * ARR_BYTES + 2 * ARR2_BYTES)  // 61440
#define NSTAGE 3
#define SMEM_TOT (NSTAGE * STG1)     // 184320

// ---------------- static device scratch ----------------
__device__ int g_count[NEXP];
__device__ int g_fill[NEXP];
__device__ int g_pbase[NEXP + 1];
__device__ int g_perm[PERM_MAX];

__device__ __nv_bfloat16 g_up_hi[(size_t)NEXP * HID * IN_DIM];
__device__ __nv_bfloat16 g_up_lo[(size_t)NEXP * HID * IN_DIM];
__device__ __nv_bfloat16 g_gt_hi[(size_t)NEXP * HID * IN_DIM];
__device__ __nv_bfloat16 g_gt_lo[(size_t)NEXP * HID * IN_DIM];
__device__ __nv_bfloat16 g_dn_hi[(size_t)NEXP * IN_DIM * HID];  // transposed [e][n][k]
__device__ __nv_bfloat16 g_dn_lo[(size_t)NEXP * IN_DIM * HID];
__device__ __nv_bfloat16 g_in_hi[(size_t)SEQ * IN_DIM];
__device__ __nv_bfloat16 g_in_lo[(size_t)SEQ * IN_DIM];
__device__ __nv_bfloat16 g_act_hi[(size_t)PERM_MAX * HID];
__device__ __nv_bfloat16 g_act_lo[(size_t)PERM_MAX * HID];
__device__ float g_y[(size_t)NTOK * IN_DIM];

// ---------------- helpers ----------------
__device__ __forceinline__ uint32_t smem_u32(const void* p) {
    uint32_t a;
    asm("{ .reg .u64 t; cvta.to.shared.u64 t, %1; cvt.u32.u64 %0, t; }" : "=r"(a) : "l"(p));
    return a;
}
__device__ __forceinline__ void cp16(uint32_t dst, const void* src, int sz) {
    asm volatile("cp.async.cg.shared.global [%0], [%1], 16, %2;" :: "r"(dst), "l"(src), "r"(sz) : "memory");
}
__device__ __forceinline__ void cp_commit() { asm volatile("cp.async.commit_group;" ::: "memory"); }
__device__ __forceinline__ void cp_wait1() { asm volatile("cp.async.wait_group 1;" ::: "memory"); }

__device__ __forceinline__ void ldm4(uint32_t* r, uint32_t a) {
    asm volatile("ldmatrix.sync.aligned.m8n8.x4.shared.b16 {%0,%1,%2,%3},[%4];"
                 : "=r"(r[0]), "=r"(r[1]), "=r"(r[2]), "=r"(r[3]) : "r"(a));
}
__device__ __forceinline__ void mma16816(float* c, const uint32_t* a, const uint32_t* b) {
    asm volatile("mma.sync.aligned.m16n8k16.row.col.f32.bf16.bf16.f32 "
                 "{%0,%1,%2,%3},{%4,%5,%6,%7},{%8,%9},{%0,%1,%2,%3};"
                 : "+f"(c[0]), "+f"(c[1]), "+f"(c[2]), "+f"(c[3])
                 : "r"(a[0]), "r"(a[1]), "r"(a[2]), "r"(a[3]), "r"(b[0]), "r"(b[1]));
}
__device__ __forceinline__ float gelu_tanh(float x) {
    float x3 = x * x * x;
    return 0.5f * x * (1.f + tanhf(0.7978845608028654f * (x + 0.044715f * x3)));
}

// ---------------- routing ----------------
__global__ void k_init() {
    int i = blockIdx.x * blockDim.x + threadIdx.x;
    if (i < NEXP) { g_count[i] = 0; g_fill[i] = 0; }
    for (int j = i; j < PERM_MAX; j += gridDim.x * blockDim.x) g_perm[j] = -1;
}
__global__ void k_count(const int* __restrict__ sel) {
    int s = blockIdx.x * blockDim.x + threadIdx.x;
    if (s < NTOK) atomicAdd(&g_count[sel[s]], 1);
}
__global__ void k_scan() {
    if (threadIdx.x == 0) {
        int acc = 0;
        g_pbase[0] = 0;
        for (int e = 0; e < NEXP; e++) {
            acc += ((g_count[e] + BM - 1) / BM) * BM;
            g_pbase[e + 1] = acc;
        }
    }
}
__global__ void k_scatter(const int* __restrict__ sel) {
    int s = blockIdx.x * blockDim.x + threadIdx.x;
    if (s < NTOK) {
        int e = sel[s];
        int pos = g_pbase[e] + atomicAdd(&g_fill[e], 1);
        g_perm[pos] = s;
    }
}

// ---------------- fp32 -> bf16 hi/lo split ----------------
__global__ void k_cvt(const float* __restrict__ src, int n4, int which) {
    __nv_bfloat16 *hi, *lo;
    if (which == 0)      { hi = g_up_hi; lo = g_up_lo; }
    else if (which == 1) { hi = g_gt_hi; lo = g_gt_lo; }
    else                 { hi = g_in_hi; lo = g_in_lo; }
    for (int i = blockIdx.x * blockDim.x + threadIdx.x; i < n4; i += gridDim.x * blockDim.x) {
        float4 v = ((const float4*)src)[i];
        __nv_bfloat16 h0 = __float2bfloat16(v.x), h1 = __float2bfloat16(v.y);
        __nv_bfloat16 h2 = __float2bfloat16(v.z), h3 = __float2bfloat16(v.w);
        __nv_bfloat162* H = (__nv_bfloat162*)(hi) + 2 * (size_t)i;
        __nv_bfloat162* L = (__nv_bfloat162*)(lo) + 2 * (size_t)i;
        H[0] = __halves2bfloat162(h0, h1);
        H[1] = __halves2bfloat162(h2, h3);
        L[0] = __halves2bfloat162(__float2bfloat16(v.x - __bfloat162float(h0)),
                                  __float2bfloat16(v.y - __bfloat162float(h1)));
        L[1] = __halves2bfloat162(__float2bfloat16(v.z - __bfloat162float(h2)),
                                  __float2bfloat16(v.w - __bfloat162float(h3)));
    }
}

// down [e][k(HID)][n(IN_DIM)] -> g_dn [e][n][k] bf16 hi/lo
__global__ void k_cvt_dnT(const float* __restrict__ down) {
    __shared__ float t[32][33];
    int e = blockIdx.z;
    int n0 = blockIdx.x * 32, k0 = blockIdx.y * 32;
    for (int i = threadIdx.y; i < 32; i += 8)
        t[i][threadIdx.x] = down[((size_t)e * HID + k0 + i) * IN_DIM + n0 + threadIdx.x];
    __syncthreads();
    for (int i = threadIdx.y; i < 32; i += 8) {
        float v = t[threadIdx.x][i];
        __nv_bfloat16 h = __float2bfloat16(v);
        size_t o = ((size_t)e * IN_DIM + n0 + i) * HID + k0 + threadIdx.x;
        g_dn_hi[o] = h;
        g_dn_lo[o] = __float2bfloat16(v - __bfloat162float(h));
    }
}

// ---------------- GEMM1 fused: x @ Wup^T and x @ Wgate^T, epilogue gelu*h -> act hi/lo ----------------
__global__ __launch_bounds__(256, 1) void k_gemm1() {
    int row0 = blockIdx.x * BM;
    if (row0 >= g_pbase[NEXP]) return;
    int nblk = blockIdx.y;

    extern __shared__ char sm[];
    __shared__ int s_tok[BM];
    int tid = threadIdx.x, lane = tid & 31, wid = tid >> 5;

    int e = 0;
    while (row0 >= g_pbase[e + 1]) e++;
    if (tid < BM) {
        int s = g_perm[row0 + tid];
        s_tok[tid] = (s >= 0) ? (s >> 1) : -1;
    }
    __syncthreads();

    size_t wof = ((size_t)e * HID + (size_t)nblk * 128) * IN_DIM;
    const __nv_bfloat16* Uh = g_up_hi + wof;
    const __nv_bfloat16* Ul = g_up_lo + wof;
    const __nv_bfloat16* Gh = g_gt_hi + wof;
    const __nv_bfloat16* Gl = g_gt_lo + wof;
    uint32_t sb = smem_u32(sm);

    auto load_stage = [&](int st, int k0) {
        uint32_t base = sb + (uint32_t)st * STG1;
        #pragma unroll
        for (int i = 0; i < 2; i++) {
            int idx = tid + i * 256;
            int r = idx >> 2, c = idx & 3;
            uint32_t d = base + (uint32_t)(r * LDK + c * 8) * 2;
            int tok = s_tok[r];
            size_t ao = (size_t)(tok < 0 ? 0 : tok) * IN_DIM + k0 + c * 8;
            int sz = tok < 0 ? 0 : 16;
            cp16(d + S1_AH, g_in_hi + ao, sz);
            cp16(d + S1_AL, g_in_lo + ao, sz);
            size_t so = (size_t)r * IN_DIM + k0 + c * 8;
            cp16(d + S1_UH, Uh + so, 16);
            cp16(d + S1_UL, Ul + so, 16);
            cp16(d + S1_GH, Gh + so, 16);
            cp16(d + S1_GL, Gl + so, 16);
        }
        cp_commit();
    };

    int wm = (wid & 1) * 64, wn = (wid >> 1) * 32;
    float acc_u[4][4][4], acc_g[4][4][4];
    #pragma unroll
    for (int a = 0; a < 4; a++)
        #pragma unroll
        for (int b = 0; b < 4; b++)
            #pragma unroll
            for (int c = 0; c < 4; c++) { acc_u[a][b][c] = 0.f; acc_g[a][b][c] = 0.f; }

    load_stage(0, 0);
    load_stage(1, BK);

    const int NS = IN_DIM / BK;  // 32
    for (int s = 0; s < NS; s++) {
        cp_wait1();
        __syncthreads();
        if (s + 2 < NS) load_stage((s + 2) % NSTAGE, (s + 2) * BK);
        else cp_commit();

        uint32_t base = sb + (uint32_t)(s % NSTAGE) * STG1;
        #pragma unroll
        for (int kh = 0; kh < 2; kh++) {
            // ---- load ALL fragments for this kh ----
            uint32_t ah[4][4], al[4][4];
            #pragma unroll
            for (int mt = 0; mt < 4; mt++) {
                uint32_t arow = wm + mt * 16 + (lane & 15);
                uint32_t acol = kh * 16 + 8 * (lane >> 4);
                uint32_t off = (arow * LDK + acol) * 2;
                ldm4(ah[mt], base + S1_AH + off);
                ldm4(al[mt], base + S1_AL + off);
            }
            uint32_t ubh[4][2], ubl[4][2], gbh[4][2], gbl[4][2];
            #pragma unroll
            for (int p = 0; p < 2; p++) {
                // x4: matrices {nt=2p k0-7, nt=2p k8-15, nt=2p+1 k0-7, nt=2p+1 k8-15}
                uint32_t quad = (uint32_t)(lane >> 3);
                uint32_t brow = wn + p * 16 + (quad >> 1) * 8 + (lane & 7);
                uint32_t bcol = kh * 16 + (quad & 1) * 8;
                uint32_t off = (brow * LDK + bcol) * 2;
                uint32_t t[4];
                ldm4(t, base + S1_UH + off);
                ubh[2*p][0]=t[0]; ubh[2*p][1]=t[1]; ubh[2*p+1][0]=t[2]; ubh[2*p+1][1]=t[3];
                ldm4(t, base + S1_UL + off);
                ubl[2*p][0]=t[0]; ubl[2*p][1]=t[1]; ubl[2*p+1][0]=t[2]; ubl[2*p+1][1]=t[3];
                ldm4(t, base + S1_GH + off);
                gbh[2*p][0]=t[0]; gbh[2*p][1]=t[1]; gbh[2*p+1][0]=t[2]; gbh[2*p+1][1]=t[3];
                ldm4(t, base + S1_GL + off);
                gbl[2*p][0]=t[0]; gbl[2*p][1]=t[1]; gbl[2*p+1][0]=t[2]; gbl[2*p+1][1]=t[3];
            }
            // ---- pass-major MMA sweeps (max accumulator reuse distance) ----
            #pragma unroll
            for (int mt = 0; mt < 4; mt++)
                #pragma unroll
                for (int nt = 0; nt < 4; nt++) mma16816(acc_u[mt][nt], ah[mt], ubh[nt]);
            #pragma unroll
            for (int mt = 0; mt < 4; mt++)
                #pragma unroll
                for (int nt = 0; nt < 4; nt++) mma16816(acc_g[mt][nt], ah[mt], gbh[nt]);
            #pragma unroll
            for (int mt = 0; mt < 4; mt++)
                #pragma unroll
                for (int nt = 0; nt < 4; nt++) mma16816(acc_u[mt][nt], ah[mt], ubl[nt]);
            #pragma unroll
            for (int mt = 0; mt < 4; mt++)
                #pragma unroll
                for (int nt = 0; nt < 4; nt++) mma16816(acc_g[mt][nt], ah[mt], gbl[nt]);
            #pragma unroll
            for (int mt = 0; mt < 4; mt++)
                #pragma unroll
                for (int nt = 0; nt < 4; nt++) mma16816(acc_u[mt][nt], al[mt], ubh[nt]);
            #pragma unroll
            for (int mt = 0; mt < 4; mt++)
                #pragma unroll
                for (int nt = 0; nt < 4; nt++) mma16816(acc_g[mt][nt], al[mt], gbh[nt]);
        }
    }

    // epilogue: act = gelu(g) * h, split into bf16 hi/lo
    #pragma unroll
    for (int mt = 0; mt < 4; mt++) {
        int gr = row0 + wm + mt * 16 + (lane >> 2);
        #pragma unroll
        for (int nt = 0; nt < 4; nt++) {
            int gc = nblk * 128 + wn + nt * 8 + (lane & 3) * 2;
            #pragma unroll
            for (int half = 0; half < 2; half++) {
                float a0 = gelu_tanh(acc_g[mt][nt][2 * half])     * acc_u[mt][nt][2 * half];
                float a1 = gelu_tanh(acc_g[mt][nt][2 * half + 1]) * acc_u[mt][nt][2 * half + 1];
                __nv_bfloat16 b0 = __float2bfloat16(a0), b1 = __float2bfloat16(a1);
                __nv_bfloat162 hp = __halves2bfloat162(b0, b1);
                __nv_bfloat162 lp = __halves2bfloat162(__float2bfloat16(a0 - __bfloat162float(b0)),
                                                       __float2bfloat16(a1 - __bfloat162float(b1)));
                size_t o = (size_t)(gr + 8 * half) * HID + gc;
                *(uint32_t*)&g_act_hi[o] = *(uint32_t*)&hp;
                *(uint32_t*)&g_act_lo[o] = *(uint32_t*)&lp;
            }
        }
    }
}

// ---------------- GEMM2: act @ downT (BN=256), scatter to g_y ----------------
__global__ __launch_bounds__(256, 1) void k_gemm2() {
    int row0 = blockIdx.x * BM;
    if (row0 >= g_pbase[NEXP]) return;
    int nblk = blockIdx.y;

    extern __shared__ char sm[];
    __shared__ int s_slot[BM];
    int tid = threadIdx.x, lane = tid & 31, wid = tid >> 5;

    int e = 0;
    while (row0 >= g_pbase[e + 1]) e++;
    if (tid < BM) s_slot[tid] = g_perm[row0 + tid];
    __syncthreads();

    size_t wof = ((size_t)e * IN_DIM + (size_t)nblk * 256) * HID;
    const __nv_bfloat16* Wh = g_dn_hi + wof;
    const __nv_bfloat16* Wl = g_dn_lo + wof;
    uint32_t sb = smem_u32(sm);

    auto load_stage = [&](int st, int k0) {
        uint32_t base = sb + (uint32_t)st * STG2;
        #pragma unroll
        for (int i = 0; i < 2; i++) {
            int idx = tid + i * 256;
            int r = idx >> 2, c = idx & 3;
            uint32_t d = base + (uint32_t)(r * LDK + c * 8) * 2;
            size_t ao = (size_t)(row0 + r) * HID + k0 + c * 8;
            cp16(d + S2_AH, g_act_hi + ao, 16);
            cp16(d + S2_AL, g_act_lo + ao, 16);
        }
        #pragma unroll
        for (int i = 0; i < 4; i++) {
            int idx = tid + i * 256;
            int r = idx >> 2, c = idx & 3;   // r 0..255
            uint32_t d = base + (uint32_t)(r * LDK + c * 8) * 2;
            size_t so = (size_t)r * HID + k0 + c * 8;
            cp16(d + S2_BH, Wh + so, 16);
            cp16(d + S2_BL, Wl + so, 16);
        }
        cp_commit();
    };

    int wm = (wid & 1) * 64, wn = (wid >> 1) * 64;
    float acc[4][8][4];
    #pragma unroll
    for (int a = 0; a < 4; a++)
        #pragma unroll
        for (int b = 0; b < 8; b++)
            #pragma unroll
            for (int c = 0; c < 4; c++) acc[a][b][c] = 0.f;

    load_stage(0, 0);
    load_stage(1, BK);

    const int NS = HID / BK;  // 64
    for (int s = 0; s < NS; s++) {
        cp_wait1();
        __syncthreads();
        if (s + 2 < NS) load_stage((s + 2) % NSTAGE, (s + 2) * BK);
        else cp_commit();

        uint32_t base = sb + (uint32_t)(s % NSTAGE) * STG2;
        #pragma unroll
        for (int kh = 0; kh < 2; kh++) {
            uint32_t ah[4][4], al[4][4];
            #pragma unroll
            for (int mt = 0; mt < 4; mt++) {
                uint32_t arow = wm + mt * 16 + (lane & 15);
                uint32_t acol = kh * 16 + 8 * (lane >> 4);
                uint32_t off = (arow * LDK + acol) * 2;
                ldm4(ah[mt], base + S2_AH + off);
                ldm4(al[mt], base + S2_AL + off);
            }
            uint32_t bh[8][2], bl[8][2];
            #pragma unroll
            for (int p = 0; p < 4; p++) {
                uint32_t quad = (uint32_t)(lane >> 3);
                uint32_t brow = wn + p * 16 + (quad >> 1) * 8 + (lane & 7);
                uint32_t bcol = kh * 16 + (quad & 1) * 8;
                uint32_t off = (brow * LDK + bcol) * 2;
                uint32_t t[4];
                ldm4(t, base + S2_BH + off);
                bh[2*p][0]=t[0]; bh[2*p][1]=t[1]; bh[2*p+1][0]=t[2]; bh[2*p+1][1]=t[3];
                ldm4(t, base + S2_BL + off);
                bl[2*p][0]=t[0]; bl[2*p][1]=t[1]; bl[2*p+1][0]=t[2]; bl[2*p+1][1]=t[3];
            }
            #pragma unroll
            for (int mt = 0; mt < 4; mt++)
                #pragma unroll
                for (int nt = 0; nt < 8; nt++) mma16816(acc[mt][nt], ah[mt], bh[nt]);
            #pragma unroll
            for (int mt = 0; mt < 4; mt++)
                #pragma unroll
                for (int nt = 0; nt < 8; nt++) mma16816(acc[mt][nt], ah[mt], bl[nt]);
            #pragma unroll
            for (int mt = 0; mt < 4; mt++)
                #pragma unroll
                for (int nt = 0; nt < 8; nt++) mma16816(acc[mt][nt], al[mt], bh[nt]);
        }
    }

    #pragma unroll
    for (int mt = 0; mt < 4; mt++) {
        int lr = wm + mt * 16 + (lane >> 2);
        int s0 = s_slot[lr];
        int s1 = s_slot[lr + 8];
        #pragma unroll
        for (int nt = 0; nt < 8; nt++) {
            int gc = nblk * 256 + wn + nt * 8 + (lane & 3) * 2;
            if (s0 >= 0)
                *(float2*)&g_y[(size_t)s0 * IN_DIM + gc] = make_float2(acc[mt][nt][0], acc[mt][nt][1]);
            if (s1 >= 0)
                *(float2*)&g_y[(size_t)s1 * IN_DIM + gc] = make_float2(acc[mt][nt][2], acc[mt][nt][3]);
        }
    }
}

// ---------------- combine ----------------
__global__ void k_combine(const float* __restrict__ wts, float* __restrict__ out) {
    size_t idx4 = ((size_t)blockIdx.x * blockDim.x + threadIdx.x) * 4;
    if (idx4 >= (size_t)SEQ * IN_DIM) return;
    int token = (int)(idx4 / IN_DIM);
    int col = (int)(idx4 % IN_DIM);
    float w0 = wts[token * 2 + 0];
    float w1 = wts[token * 2 + 1];
    float4 y0 = *(const float4*)&g_y[(size_t)(token * 2 + 0) * IN_DIM + col];
    float4 y1 = *(const float4*)&g_y[(size_t)(token * 2 + 1) * IN_DIM + col];
    float4 r;
    r.x = w0 * y0.x + w1 * y1.x;
    r.y = w0 * y0.y + w1 * y1.y;
    r.z = w0 * y0.z + w1 * y1.z;
    r.w = w0 * y0.w + w1 * y1.w;
    *(float4*)&out[idx4] = r;
}

// ---------------- launch ----------------
extern "C" void kernel_launch(void* const* d_in, const int* in_sizes, int n_in,
                              void* d_out, int out_size) {
    const float* inp  = (const float*)d_in[0];
    const float* wts  = (const float*)d_in[1];
    const float* up   = (const float*)d_in[2];
    const float* gate = (const float*)d_in[3];
    const float* down = (const float*)d_in[4];
    const int*   sel  = (const int*)d_in[5];
    float* out = (float*)d_out;

    cudaFuncSetAttribute(k_gemm1, cudaFuncAttributeMaxDynamicSharedMemorySize, SMEM_TOT);
    cudaFuncSetAttribute(k_gemm2, cudaFuncAttributeMaxDynamicSharedMemorySize, SMEM_TOT);

    k_init<<<64, 256>>>();
    k_count<<<NTOK / 256, 256>>>(sel);
    k_scan<<<1, 32>>>();
    k_scatter<<<NTOK / 256, 256>>>(sel);

    k_cvt<<<4096, 256>>>(up,   (int)((size_t)NEXP * HID * IN_DIM / 4), 0);
    k_cvt<<<4096, 256>>>(gate, (int)((size_t)NEXP * HID * IN_DIM / 4), 1);
    k_cvt<<<2048, 256>>>(inp,  SEQ * IN_DIM / 4, 2);
    k_cvt_dnT<<<dim3(IN_DIM / 32, HID / 32, NEXP), dim3(32, 8)>>>(down);

    k_gemm1<<<dim3(PERM_MAX / BM, HID / 128), 256, SMEM_TOT>>>();
    k_gemm2<<<dim3(PERM_MAX / BM, IN_DIM / 256), 256, SMEM_TOT>>>();
    k_combine<<<(SEQ * IN_DIM / 4 + 255) / 256, 256>>>(wts, out);
}